// round 1
// baseline (speedup 1.0000x reference)
#include <cuda_runtime.h>
#include <math.h>

#define BATCH 64
#define KCODES 512
#define DDIM 64

// ---------------- scratch (device globals; no allocation allowed) ----------------
__device__ float d_h1 [BATCH * 64 * 64 * 64];   // (B,64,64,64)  also tc1 output
__device__ float d_a  [BATCH * 128 * 32 * 32];  // (B,128,32,32) ping
__device__ float d_b  [BATCH * 128 * 32 * 32];  // (B,128,32,32) pong
__device__ float d_mid[BATCH * 64 * 32 * 32];   // res-block mid (B,64,32,32)
__device__ float d_ze [BATCH * 64 * 32 * 32];   // encoder latent
__device__ float d_zq [BATCH * 64 * 32 * 32];   // quantized latent
__device__ float d_enorm [KCODES];
__device__ float d_counts[KCODES];
__device__ float d_sqsum[1];

// ---------------- generic direct conv ----------------
// out(n, co, oy, ox) = [bias] + sum_ci sum_tap relu?(in) * w
// Weights staged wholly in smem as [ci][tap][co_blk] for broadcast LDS.128.
template<int CIN, int COUT, int KS, int STR, int PAD, int IH, int IW, int CO_BLK,
         bool RELU_IN, bool RELU_OUT, bool HAS_BIAS, bool ADD_RES>
__global__ void conv_k(const float* __restrict__ in, const float* __restrict__ w,
                       const float* __restrict__ bias, const float* __restrict__ res,
                       float* __restrict__ out)
{
    static_assert(CO_BLK % 4 == 0, "co blk mult of 4");
    static_assert(COUT % CO_BLK == 0, "cout divisible");
    constexpr int OH = (IH + 2 * PAD - KS) / STR + 1;
    constexpr int OW = (IW + 2 * PAD - KS) / STR + 1;
    constexpr int KK = KS * KS;
    extern __shared__ float sw[];  // [CIN][KK][CO_BLK]

    const int n   = blockIdx.z;
    const int co0 = blockIdx.y * CO_BLK;
    const int tid = threadIdx.x;

    for (int i = tid; i < CIN * KK * CO_BLK; i += blockDim.x) {
        int co = i % CO_BLK;
        int t  = (i / CO_BLK) % KK;
        int ci = i / (CO_BLK * KK);
        sw[i] = w[((size_t)(co0 + co) * CIN + ci) * KK + t];
    }
    __syncthreads();

    int p = blockIdx.x * blockDim.x + tid;
    if (p >= OH * OW) return;
    int oy = p / OW, ox = p % OW;
    int iy0 = oy * STR - PAD, ix0 = ox * STR - PAD;

    // Precompute tap offsets + validity once
    int  off[KK];
    bool ok [KK];
#pragma unroll
    for (int t = 0; t < KK; t++) {
        int ky = t / KS, kx = t % KS;
        int y = iy0 + ky, x = ix0 + kx;
        ok[t]  = (y >= 0) && (y < IH) && (x >= 0) && (x < IW);
        off[t] = y * IW + x;
    }

    float acc[CO_BLK];
#pragma unroll
    for (int c = 0; c < CO_BLK; c++) acc[c] = 0.f;

    const float* inb = in + (size_t)n * CIN * IH * IW;
    for (int ci = 0; ci < CIN; ci++) {
        float v[KK];
        const float* inc = inb + (size_t)ci * IH * IW;
#pragma unroll
        for (int t = 0; t < KK; t++) {
            float val = ok[t] ? inc[off[t]] : 0.f;
            if (RELU_IN) val = fmaxf(val, 0.f);
            v[t] = val;
        }
        const float4* w4 = (const float4*)(sw + (size_t)ci * KK * CO_BLK);
#pragma unroll
        for (int t = 0; t < KK; t++) {
#pragma unroll
            for (int q = 0; q < CO_BLK / 4; q++) {
                float4 ww = w4[t * (CO_BLK / 4) + q];
                acc[4 * q + 0] += v[t] * ww.x;
                acc[4 * q + 1] += v[t] * ww.y;
                acc[4 * q + 2] += v[t] * ww.z;
                acc[4 * q + 3] += v[t] * ww.w;
            }
        }
    }

    float* ob = out + ((size_t)n * COUT + co0) * OH * OW + p;
#pragma unroll
    for (int c = 0; c < CO_BLK; c++) {
        float r = acc[c];
        if (HAS_BIAS) r += bias[co0 + c];
        if (ADD_RES)  r += res[((size_t)n * COUT + co0 + c) * OH * OW + p];
        if (RELU_OUT) r = fmaxf(r, 0.f);
        ob[(size_t)c * OH * OW] = r;
    }
}

// ---------------- transposed conv, k=4, s=2, p=1 (gather form) ----------------
// out(oy,ox) gets 4 taps: ky in {par(oy), par(oy)+2}, iy = (oy+1-ky)/2 (if valid)
// weight layout (CIN, COUT, 4, 4)
template<int CIN, int COUT, int IH, int IW, int CO_BLK, bool RELU_IN, bool RELU_OUT>
__global__ void convt_k(const float* __restrict__ in, const float* __restrict__ w,
                        const float* __restrict__ bias, float* __restrict__ out)
{
    static_assert(CO_BLK % 4 == 0, "co blk mult of 4");
    constexpr int OH = IH * 2, OW = IW * 2;
    extern __shared__ float sw[];  // [CIN][16][CO_BLK]

    const int n   = blockIdx.z;
    const int co0 = blockIdx.y * CO_BLK;
    const int tid = threadIdx.x;

    for (int i = tid; i < CIN * 16 * CO_BLK; i += blockDim.x) {
        int co = i % CO_BLK;
        int t  = (i / CO_BLK) % 16;
        int ci = i / (CO_BLK * 16);
        float val = 0.f;
        if (co0 + co < COUT)
            val = w[((size_t)ci * COUT + (co0 + co)) * 16 + t];
        sw[i] = val;
    }
    __syncthreads();

    int p = blockIdx.x * blockDim.x + tid;
    if (p >= OH * OW) return;
    int oy = p / OW, ox = p % OW;
    int kpy = (oy + 1) & 1, kpx = (ox + 1) & 1;

    int  iy[2], ix[2];
    bool vy[2], vx[2];
#pragma unroll
    for (int j = 0; j < 2; j++) {
        int ky = kpy + 2 * j, yy = oy + 1 - ky;
        iy[j] = yy >> 1; vy[j] = (yy >= 0) && (iy[j] < IH);
        int kx = kpx + 2 * j, xx = ox + 1 - kx;
        ix[j] = xx >> 1; vx[j] = (xx >= 0) && (ix[j] < IW);
    }

    float acc[CO_BLK];
#pragma unroll
    for (int c = 0; c < CO_BLK; c++) acc[c] = 0.f;

    const float* inb = in + (size_t)n * CIN * IH * IW;
    for (int ci = 0; ci < CIN; ci++) {
        const float* inc = inb + (size_t)ci * IH * IW;
        float v[4];
#pragma unroll
        for (int a = 0; a < 2; a++)
#pragma unroll
            for (int bb = 0; bb < 2; bb++) {
                float val = 0.f;
                if (vy[a] && vx[bb]) val = inc[iy[a] * IW + ix[bb]];
                if (RELU_IN) val = fmaxf(val, 0.f);
                v[a * 2 + bb] = val;
            }
        const float4* w4 = (const float4*)(sw + (size_t)ci * 16 * CO_BLK);
#pragma unroll
        for (int a = 0; a < 2; a++)
#pragma unroll
            for (int bb = 0; bb < 2; bb++) {
                int t = (kpy + 2 * a) * 4 + (kpx + 2 * bb);
                float vv = v[a * 2 + bb];
#pragma unroll
                for (int q = 0; q < CO_BLK / 4; q++) {
                    float4 ww = w4[t * (CO_BLK / 4) + q];
                    acc[4 * q + 0] += vv * ww.x;
                    acc[4 * q + 1] += vv * ww.y;
                    acc[4 * q + 2] += vv * ww.z;
                    acc[4 * q + 3] += vv * ww.w;
                }
            }
    }

    float* ob = out + ((size_t)n * COUT + co0) * OH * OW + p;
#pragma unroll
    for (int c = 0; c < CO_BLK; c++) {
        if (co0 + c < COUT) {
            float r = acc[c] + bias[co0 + c];
            if (RELU_OUT) r = fmaxf(r, 0.f);
            ob[(size_t)c * OH * OW] = r;
        }
    }
}

// ---------------- VQ ----------------
__global__ void vq_init_k(const float* __restrict__ E, float* __restrict__ enorm,
                          float* __restrict__ counts, float* __restrict__ sqsum)
{
    int k = blockIdx.x * blockDim.x + threadIdx.x;
    if (k < KCODES) {
        float s = 0.f;
#pragma unroll
        for (int d = 0; d < DDIM; d++) { float e = E[k * DDIM + d]; s += e * e; }
        enorm[k] = s;
        counts[k] = 0.f;
    }
    if (k == 0) sqsum[0] = 0.f;
}

// one thread = one latent row (64 dims in regs); E streamed via smem in 128-code chunks
__global__ void vq_k(const float* __restrict__ ze, const float* __restrict__ E,
                     const float* __restrict__ enorm, float* __restrict__ zq,
                     float* __restrict__ counts, float* __restrict__ sqsum)
{
    __shared__ float sE[128 * DDIM];
    __shared__ float sN[128];
    __shared__ float sred[8];

    const int tid = threadIdx.x;
    const int r = blockIdx.x * blockDim.x + tid;  // 0..65535
    const int n = r >> 10, hw = r & 1023;

    const float* zb = ze + (size_t)n * DDIM * 1024 + hw;
    float z[DDIM];
#pragma unroll
    for (int d = 0; d < DDIM; d++) z[d] = zb[(size_t)d * 1024];
    float zn = 0.f;
#pragma unroll
    for (int d = 0; d < DDIM; d++) zn += z[d] * z[d];

    float best = 3.4e38f;
    int bidx = 0;
    for (int c = 0; c < KCODES / 128; c++) {
        __syncthreads();
        for (int i = tid; i < 128 * DDIM; i += blockDim.x) sE[i] = E[c * 128 * DDIM + i];
        for (int i = tid; i < 128; i += blockDim.x) sN[i] = enorm[c * 128 + i];
        __syncthreads();
        for (int k = 0; k < 128; k++) {
            const float4* e4 = (const float4*)(sE + k * DDIM);
            float a0 = 0.f, a1 = 0.f, a2 = 0.f, a3 = 0.f;
#pragma unroll
            for (int m = 0; m < DDIM / 4; m++) {
                float4 e = e4[m];
                a0 += z[4 * m + 0] * e.x;
                a1 += z[4 * m + 1] * e.y;
                a2 += z[4 * m + 2] * e.z;
                a3 += z[4 * m + 3] * e.w;
            }
            float dist = zn + sN[k] - 2.f * ((a0 + a1) + (a2 + a3));
            if (dist < best) { best = dist; bidx = c * 128 + k; }
        }
    }

    // gather code, write Zq (NCHW), accumulate direct squared error
    float local = 0.f;
    const float* eb = E + (size_t)bidx * DDIM;
    float* zqb = zq + (size_t)n * DDIM * 1024 + hw;
#pragma unroll
    for (int d = 0; d < DDIM; d++) {
        float e = eb[d];
        zqb[(size_t)d * 1024] = e;
        float df = e - z[d];
        local += df * df;
    }
    atomicAdd(&counts[bidx], 1.f);

#pragma unroll
    for (int o = 16; o; o >>= 1) local += __shfl_down_sync(0xffffffffu, local, o);
    if ((tid & 31) == 0) sred[tid >> 5] = local;
    __syncthreads();
    if (tid < 8) {
        local = sred[tid];
#pragma unroll
        for (int o = 4; o; o >>= 1) local += __shfl_down_sync(0xffu, local, o);
        if (tid == 0) atomicAdd(sqsum, local);
    }
}

__global__ void finalize_k(const float* __restrict__ counts, const float* __restrict__ sqsum,
                           float* __restrict__ out)
{
    __shared__ float sred[16];
    int tid = threadIdx.x;  // 512 threads
    float p = counts[tid] * (1.f / 65536.f);
    float term = -p * log2f(p + 1e-10f);
#pragma unroll
    for (int o = 16; o; o >>= 1) term += __shfl_down_sync(0xffffffffu, term, o);
    if ((tid & 31) == 0) sred[tid >> 5] = term;
    __syncthreads();
    if (tid < 16) {
        term = sred[tid];
#pragma unroll
        for (int o = 8; o; o >>= 1) term += __shfl_down_sync(0xffffu, term, o);
        if (tid == 0) {
            float H = term;
            float mse = sqsum[0] / (65536.f * 64.f);
            const int base = 1 + BATCH * 3 * 128 * 128;
            out[0] = 1.25f * mse;       // q + BETA*e, both == mse in forward
            out[base + 0] = mse;        // e_latent_loss
            out[base + 1] = mse;        // q_latent_loss
            out[base + 2] = exp2f(H);   // est_words
        }
    }
}

// ---------------- launch ----------------
extern "C" void kernel_launch(void* const* d_in, const int* in_sizes, int n_in,
                              void* d_out, int out_size)
{
    const float* x        = (const float*)d_in[0];
    const float* enc_w1   = (const float*)d_in[1];
    const float* enc_b1   = (const float*)d_in[2];
    const float* enc_w2   = (const float*)d_in[3];
    const float* enc_b2   = (const float*)d_in[4];
    const float* enc_w3   = (const float*)d_in[5];
    const float* enc_b3   = (const float*)d_in[6];
    const float* enc_w4   = (const float*)d_in[7];
    const float* enc_b4   = (const float*)d_in[8];
    const float* enc_rw1  = (const float*)d_in[9];
    const float* enc_rw2  = (const float*)d_in[10];
    const float* enc_adjw = (const float*)d_in[11];
    const float* enc_adjb = (const float*)d_in[12];
    const float* E        = (const float*)d_in[13];
    const float* dec_adjw = (const float*)d_in[14];
    const float* dec_adjb = (const float*)d_in[15];
    const float* dec_rw1  = (const float*)d_in[16];
    const float* dec_rw2  = (const float*)d_in[17];
    const float* tc1_w    = (const float*)d_in[18];
    const float* tc1_b    = (const float*)d_in[19];
    const float* tc2_w    = (const float*)d_in[20];
    const float* tc2_b    = (const float*)d_in[21];

    float* out   = (float*)d_out;
    float* recon = out + 1;

    float *h1, *a, *b, *mid, *ze, *zq, *enorm, *counts, *sqsum;
    cudaGetSymbolAddress((void**)&h1,     d_h1);
    cudaGetSymbolAddress((void**)&a,      d_a);
    cudaGetSymbolAddress((void**)&b,      d_b);
    cudaGetSymbolAddress((void**)&mid,    d_mid);
    cudaGetSymbolAddress((void**)&ze,     d_ze);
    cudaGetSymbolAddress((void**)&zq,     d_zq);
    cudaGetSymbolAddress((void**)&enorm,  d_enorm);
    cudaGetSymbolAddress((void**)&counts, d_counts);
    cudaGetSymbolAddress((void**)&sqsum,  d_sqsum);

    const int TPB = 256;

    // ---- encoder ----
    // conv1: (B,3,128,128) -> relu -> (B,64,64,64)
    conv_k<3, 64, 4, 2, 1, 128, 128, 16, false, true, true, false>
        <<<dim3(4096 / TPB, 64 / 16, BATCH), TPB, 3 * 16 * 16 * 4>>>(x, enc_w1, enc_b1, nullptr, h1);

    // conv2: -> relu -> (B,128,32,32)
    {
        auto f = conv_k<64, 128, 4, 2, 1, 64, 64, 16, false, true, true, false>;
        cudaFuncSetAttribute((const void*)f, cudaFuncAttributeMaxDynamicSharedMemorySize, 64 * 16 * 16 * 4);
        f<<<dim3(1024 / TPB, 128 / 16, BATCH), TPB, 64 * 16 * 16 * 4>>>(h1, enc_w2, enc_b2, nullptr, a);
    }
    // conv3: 3x3 relu
    {
        auto f = conv_k<128, 128, 3, 1, 1, 32, 32, 16, false, true, true, false>;
        cudaFuncSetAttribute((const void*)f, cudaFuncAttributeMaxDynamicSharedMemorySize, 128 * 9 * 16 * 4);
        f<<<dim3(1024 / TPB, 128 / 16, BATCH), TPB, 128 * 9 * 16 * 4>>>(a, enc_w3, enc_b3, nullptr, b);
    }
    // conv4: 3x3 no relu
    {
        auto f = conv_k<128, 128, 3, 1, 1, 32, 32, 16, false, false, true, false>;
        cudaFuncSetAttribute((const void*)f, cudaFuncAttributeMaxDynamicSharedMemorySize, 128 * 9 * 16 * 4);
        f<<<dim3(1024 / TPB, 128 / 16, BATCH), TPB, 128 * 9 * 16 * 4>>>(b, enc_w4, enc_b4, nullptr, a);
    }

    auto res_r1 = conv_k<128, 64, 3, 1, 1, 32, 32, 16, true, false, false, false>;
    cudaFuncSetAttribute((const void*)res_r1, cudaFuncAttributeMaxDynamicSharedMemorySize, 128 * 9 * 16 * 4);
    auto res_r2 = conv_k<64, 128, 1, 1, 0, 32, 32, 16, true, false, false, true>;

    // encoder res stack (2 blocks), in-place on `a`
    for (int i = 0; i < 2; i++) {
        res_r1<<<dim3(1024 / TPB, 64 / 16, BATCH), TPB, 128 * 9 * 16 * 4>>>(
            a, enc_rw1 + (size_t)i * 64 * 128 * 9, nullptr, nullptr, mid);
        res_r2<<<dim3(1024 / TPB, 128 / 16, BATCH), TPB, 64 * 1 * 16 * 4>>>(
            mid, enc_rw2 + (size_t)i * 128 * 64, nullptr, a, a);
    }
    // enc_adj: relu_in 1x1 -> Ze (B,64,32,32)
    conv_k<128, 64, 1, 1, 0, 32, 32, 16, true, false, true, false>
        <<<dim3(1024 / TPB, 64 / 16, BATCH), TPB, 128 * 1 * 16 * 4>>>(a, enc_adjw, enc_adjb, nullptr, ze);

    // ---- VQ ----
    vq_init_k<<<2, 256>>>(E, enorm, counts, sqsum);
    vq_k<<<65536 / 256, 256>>>(ze, E, enorm, zq, counts, sqsum);

    // ---- decoder ----
    // dec_adj 3x3 64->128 bias
    conv_k<64, 128, 3, 1, 1, 32, 32, 16, false, false, true, false>
        <<<dim3(1024 / TPB, 128 / 16, BATCH), TPB, 64 * 9 * 16 * 4>>>(zq, dec_adjw, dec_adjb, nullptr, a);

    for (int i = 0; i < 2; i++) {
        res_r1<<<dim3(1024 / TPB, 64 / 16, BATCH), TPB, 128 * 9 * 16 * 4>>>(
            a, dec_rw1 + (size_t)i * 64 * 128 * 9, nullptr, nullptr, mid);
        res_r2<<<dim3(1024 / TPB, 128 / 16, BATCH), TPB, 64 * 1 * 16 * 4>>>(
            mid, dec_rw2 + (size_t)i * 128 * 64, nullptr, a, a);
    }

    // tc1: relu_in (final res relu), convT 128->64, relu_out -> (B,64,64,64)
    {
        auto f = convt_k<128, 64, 32, 32, 8, true, true>;
        cudaFuncSetAttribute((const void*)f, cudaFuncAttributeMaxDynamicSharedMemorySize, 128 * 16 * 8 * 4);
        f<<<dim3(4096 / TPB, 64 / 8, BATCH), TPB, 128 * 16 * 8 * 4>>>(a, tc1_w, tc1_b, h1);
    }
    // tc2: convT 64->3 -> recon (B,3,128,128)
    convt_k<64, 3, 64, 64, 4, false, false>
        <<<dim3(16384 / TPB, 1, BATCH), TPB, 64 * 16 * 4 * 4>>>(h1, tc2_w, tc2_b, recon);

    // ---- scalars ----
    finalize_k<<<1, 512>>>(counts, sqsum, out);
}

// round 2
// speedup vs baseline: 1.0370x; 1.0370x over previous
#include <cuda_runtime.h>
#include <math.h>

#define BATCH 64
#define KCODES 512
#define DDIM 64

// ---------------- scratch (device globals; no allocation allowed) ----------------
__device__ float d_h1 [BATCH * 64 * 64 * 64];   // (B,64,64,64)  also tc1 output
__device__ float d_a  [BATCH * 128 * 32 * 32];  // (B,128,32,32) ping
__device__ float d_b  [BATCH * 128 * 32 * 32];  // (B,128,32,32) pong
__device__ float d_mid[BATCH * 64 * 32 * 32];   // res-block mid (B,64,32,32)
__device__ float d_ze [BATCH * 64 * 32 * 32];   // encoder latent
__device__ float d_zq [BATCH * 64 * 32 * 32];   // quantized latent
__device__ float d_enorm [KCODES];
__device__ float d_counts[KCODES];
__device__ float d_sqsum[1];

// ---------------- packed f32x2 helpers ----------------
__device__ __forceinline__ unsigned long long pk2(float a, float b) {
    unsigned long long r;
    asm("mov.b64 %0, {%1, %2};" : "=l"(r) : "f"(a), "f"(b));
    return r;
}
__device__ __forceinline__ void fma2(unsigned long long& d, unsigned long long a, unsigned long long b) {
    asm("fma.rn.f32x2 %0, %1, %2, %0;" : "+l"(d) : "l"(a), "l"(b));
}
__device__ __forceinline__ float2 upk2(unsigned long long a) {
    float2 f;
    asm("mov.b64 {%0, %1}, %2;" : "=f"(f.x), "=f"(f.y) : "l"(a));
    return f;
}

// ---------------- generic direct conv, PX pixels/thread, f32x2 MACs ----------------
// Weights staged in smem as [ci][tap][co_blk]; read as ulonglong2 (LDS.128 broadcast).
template<int CIN, int COUT, int KS, int STR, int PAD, int IH, int IW, int CO_BLK, int PX,
         bool RELU_IN, bool RELU_OUT, bool HAS_BIAS, bool ADD_RES>
__global__ void __launch_bounds__(128) conv_k(
    const float* __restrict__ in, const float* __restrict__ w,
    const float* __restrict__ bias, const float* __restrict__ res,
    float* __restrict__ out)
{
    static_assert(CO_BLK % 4 == 0, "co blk mult of 4");
    static_assert(COUT % CO_BLK == 0, "cout divisible");
    constexpr int OH = (IH + 2 * PAD - KS) / STR + 1;
    constexpr int OW = (IW + 2 * PAD - KS) / STR + 1;
    static_assert(OW % PX == 0, "row-aligned pixel tiles");
    constexpr int KK = KS * KS;
    constexpr int COLS = STR * (PX - 1) + KS;
    extern __shared__ float sw[];  // [CIN][KK][CO_BLK]

    const int n   = blockIdx.z;
    const int co0 = blockIdx.y * CO_BLK;
    const int tid = threadIdx.x;

    for (int i = tid; i < CIN * KK * CO_BLK; i += blockDim.x) {
        int co = i % CO_BLK;
        int t  = (i / CO_BLK) % KK;
        int ci = i / (CO_BLK * KK);
        sw[i] = w[((size_t)(co0 + co) * CIN + ci) * KK + t];
    }
    __syncthreads();

    int p0 = (blockIdx.x * blockDim.x + tid) * PX;
    if (p0 >= OH * OW) return;
    int oy = p0 / OW, ox0 = p0 % OW;
    int iy0 = oy * STR - PAD, ix0 = ox0 * STR - PAD;

    bool rok[KS]; int roff[KS];
#pragma unroll
    for (int ky = 0; ky < KS; ky++) {
        int y = iy0 + ky;
        rok[ky] = (y >= 0) && (y < IH);
        roff[ky] = y * IW;
    }
    bool cok[COLS]; int coff[COLS];
#pragma unroll
    for (int cx = 0; cx < COLS; cx++) {
        int x = ix0 + cx;
        cok[cx] = (x >= 0) && (x < IW);
        coff[cx] = x;
    }

    unsigned long long acc[PX][CO_BLK / 2];
#pragma unroll
    for (int px = 0; px < PX; px++)
#pragma unroll
        for (int j = 0; j < CO_BLK / 2; j++) acc[px][j] = 0ull;

    const float* inb = in + (size_t)n * CIN * IH * IW;
    for (int ci = 0; ci < CIN; ci++) {
        const float* inc = inb + (size_t)ci * IH * IW;
        unsigned long long pv[KS][COLS];
#pragma unroll
        for (int ky = 0; ky < KS; ky++)
#pragma unroll
            for (int cx = 0; cx < COLS; cx++) {
                float val = (rok[ky] && cok[cx]) ? inc[roff[ky] + coff[cx]] : 0.f;
                if (RELU_IN) val = fmaxf(val, 0.f);
                pv[ky][cx] = pk2(val, val);
            }
        const ulonglong2* wt = (const ulonglong2*)(sw + (size_t)ci * KK * CO_BLK);
#pragma unroll
        for (int ky = 0; ky < KS; ky++)
#pragma unroll
            for (int kx = 0; kx < KS; kx++) {
                const int t = ky * KS + kx;
#pragma unroll
                for (int q = 0; q < CO_BLK / 4; q++) {
                    ulonglong2 ww = wt[t * (CO_BLK / 4) + q];
#pragma unroll
                    for (int px = 0; px < PX; px++) {
                        unsigned long long vv = pv[ky][px * STR + kx];
                        fma2(acc[px][2 * q + 0], vv, ww.x);
                        fma2(acc[px][2 * q + 1], vv, ww.y);
                    }
                }
            }
    }

    float bco[CO_BLK];
#pragma unroll
    for (int c = 0; c < CO_BLK; c++) bco[c] = HAS_BIAS ? bias[co0 + c] : 0.f;

    float* ob = out + ((size_t)n * COUT + co0) * OH * OW + p0;
#pragma unroll
    for (int j = 0; j < CO_BLK / 2; j++) {
        float r0[PX], r1[PX];
#pragma unroll
        for (int px = 0; px < PX; px++) {
            float2 f = upk2(acc[px][j]);
            r0[px] = f.x + bco[2 * j + 0];
            r1[px] = f.y + bco[2 * j + 1];
            if (ADD_RES) {
                r0[px] += res[((size_t)n * COUT + co0 + 2 * j + 0) * OH * OW + p0 + px];
                r1[px] += res[((size_t)n * COUT + co0 + 2 * j + 1) * OH * OW + p0 + px];
            }
            if (RELU_OUT) { r0[px] = fmaxf(r0[px], 0.f); r1[px] = fmaxf(r1[px], 0.f); }
        }
        float* o0 = ob + (size_t)(2 * j + 0) * OH * OW;
        float* o1 = ob + (size_t)(2 * j + 1) * OH * OW;
        if (PX == 4) {
            *(float4*)o0 = make_float4(r0[0], r0[1], r0[2], r0[3 % PX]);
            *(float4*)o1 = make_float4(r1[0], r1[1], r1[2], r1[3 % PX]);
        } else if (PX == 2) {
            *(float2*)o0 = make_float2(r0[0], r0[1 % PX]);
            *(float2*)o1 = make_float2(r1[0], r1[1 % PX]);
        } else {
#pragma unroll
            for (int px = 0; px < PX; px++) { o0[px] = r0[px]; o1[px] = r1[px]; }
        }
    }
}

// ---------------- transposed conv, k=4, s=2, p=1 (gather), PX pixels, f32x2 ----------------
// weight layout (CIN, COUT, 4, 4)
template<int CIN, int COUT, int IH, int IW, int CO_BLK, int PX,
         bool RELU_IN, bool RELU_OUT, bool VEC_ST>
__global__ void __launch_bounds__(128) convt_k(
    const float* __restrict__ in, const float* __restrict__ w,
    const float* __restrict__ bias, float* __restrict__ out)
{
    static_assert(CO_BLK % 4 == 0, "co blk mult of 4");
    static_assert(PX % 2 == 0, "pixel pairs");
    constexpr int OH = IH * 2, OW = IW * 2;
    static_assert(OW % PX == 0, "row-aligned");
    extern __shared__ float sw[];  // [CIN][16][CO_BLK]

    const int n   = blockIdx.z;
    const int co0 = blockIdx.y * CO_BLK;
    const int tid = threadIdx.x;

    for (int i = tid; i < CIN * 16 * CO_BLK; i += blockDim.x) {
        int co = i % CO_BLK;
        int t  = (i / CO_BLK) % 16;
        int ci = i / (CO_BLK * 16);
        float val = 0.f;
        if (co0 + co < COUT)
            val = w[((size_t)ci * COUT + (co0 + co)) * 16 + t];
        sw[i] = val;
    }
    __syncthreads();

    int p0 = (blockIdx.x * blockDim.x + tid) * PX;
    if (p0 >= OH * OW) return;
    int oy = p0 / OW, ox0 = p0 % OW;
    const int kpy = (oy + 1) & 1;
    const int kp0 = (ox0 + 1) & 1;  // parity of pixel 0; alternates per pixel

    int iy[2]; bool vy[2];
#pragma unroll
    for (int a = 0; a < 2; a++) {
        int ky = kpy + 2 * a, yy = oy + 1 - ky;
        iy[a] = yy >> 1; vy[a] = (yy >= 0) && (iy[a] < IH);
    }
    int ixp[PX][2]; bool vxp[PX][2];
#pragma unroll
    for (int px = 0; px < PX; px++) {
        int ox = ox0 + px;
        int kpx = (kp0 + px) & 1;
#pragma unroll
        for (int b = 0; b < 2; b++) {
            int kx = kpx + 2 * b, xx = ox + 1 - kx;
            ixp[px][b] = xx >> 1; vxp[px][b] = (xx >= 0) && (ixp[px][b] < IW);
        }
    }

    unsigned long long acc[PX][CO_BLK / 2];
#pragma unroll
    for (int px = 0; px < PX; px++)
#pragma unroll
        for (int j = 0; j < CO_BLK / 2; j++) acc[px][j] = 0ull;

    const float* inb = in + (size_t)n * CIN * IH * IW;
    for (int ci = 0; ci < CIN; ci++) {
        const float* inc = inb + (size_t)ci * IH * IW;
        unsigned long long pv[PX][4];
#pragma unroll
        for (int px = 0; px < PX; px++)
#pragma unroll
            for (int a = 0; a < 2; a++)
#pragma unroll
                for (int b = 0; b < 2; b++) {
                    float val = 0.f;
                    if (vy[a] && vxp[px][b]) val = inc[iy[a] * IW + ixp[px][b]];
                    if (RELU_IN) val = fmaxf(val, 0.f);
                    pv[px][a * 2 + b] = pk2(val, val);
                }
        const ulonglong2* wt = (const ulonglong2*)(sw + (size_t)ci * 16 * CO_BLK);
        // group pixels by x-parity so each weight load feeds PX/2 pixels
#pragma unroll
        for (int g = 0; g < 2; g++) {
            const int kpxg = (kp0 + g) & 1;
#pragma unroll
            for (int a = 0; a < 2; a++)
#pragma unroll
                for (int b = 0; b < 2; b++) {
                    const int t = (kpy + 2 * a) * 4 + (kpxg + 2 * b);
#pragma unroll
                    for (int q = 0; q < CO_BLK / 4; q++) {
                        ulonglong2 ww = wt[t * (CO_BLK / 4) + q];
#pragma unroll
                        for (int px = g; px < PX; px += 2) {
                            unsigned long long vv = pv[px][a * 2 + b];
                            fma2(acc[px][2 * q + 0], vv, ww.x);
                            fma2(acc[px][2 * q + 1], vv, ww.y);
                        }
                    }
                }
        }
    }

    float bco[CO_BLK];
#pragma unroll
    for (int c = 0; c < CO_BLK; c++)
        bco[c] = (co0 + c < COUT) ? bias[co0 + c] : 0.f;

    float* ob = out + ((size_t)n * COUT + co0) * OH * OW + p0;
#pragma unroll
    for (int j = 0; j < CO_BLK / 2; j++) {
        float r0[PX], r1[PX];
#pragma unroll
        for (int px = 0; px < PX; px++) {
            float2 f = upk2(acc[px][j]);
            r0[px] = f.x + bco[2 * j + 0];
            r1[px] = f.y + bco[2 * j + 1];
            if (RELU_OUT) { r0[px] = fmaxf(r0[px], 0.f); r1[px] = fmaxf(r1[px], 0.f); }
        }
        float* o0 = ob + (size_t)(2 * j + 0) * OH * OW;
        float* o1 = ob + (size_t)(2 * j + 1) * OH * OW;
        if (VEC_ST && PX == 4) {
            if (co0 + 2 * j + 0 < COUT) *(float4*)o0 = make_float4(r0[0], r0[1], r0[2], r0[3 % PX]);
            if (co0 + 2 * j + 1 < COUT) *(float4*)o1 = make_float4(r1[0], r1[1], r1[2], r1[3 % PX]);
        } else {
#pragma unroll
            for (int px = 0; px < PX; px++) {
                if (co0 + 2 * j + 0 < COUT) o0[px] = r0[px];
                if (co0 + 2 * j + 1 < COUT) o1[px] = r1[px];
            }
        }
    }
}

// ---------------- VQ ----------------
__global__ void vq_init_k(const float* __restrict__ E, float* __restrict__ enorm,
                          float* __restrict__ counts, float* __restrict__ sqsum)
{
    int k = blockIdx.x * blockDim.x + threadIdx.x;
    if (k < KCODES) {
        float s = 0.f;
#pragma unroll
        for (int d = 0; d < DDIM; d++) { float e = E[k * DDIM + d]; s += e * e; }
        enorm[k] = s;
        counts[k] = 0.f;
    }
    if (k == 0) sqsum[0] = 0.f;
}

// one thread = one latent row (64 dims in regs); E streamed via smem in 128-code chunks
__global__ void vq_k(const float* __restrict__ ze, const float* __restrict__ E,
                     const float* __restrict__ enorm, float* __restrict__ zq,
                     float* __restrict__ counts, float* __restrict__ sqsum)
{
    __shared__ float sE[128 * DDIM];
    __shared__ float sN[128];
    __shared__ float sred[8];

    const int tid = threadIdx.x;
    const int r = blockIdx.x * blockDim.x + tid;  // 0..65535
    const int n = r >> 10, hw = r & 1023;

    const float* zb = ze + (size_t)n * DDIM * 1024 + hw;
    float z[DDIM];
#pragma unroll
    for (int d = 0; d < DDIM; d++) z[d] = zb[(size_t)d * 1024];
    float zn = 0.f;
#pragma unroll
    for (int d = 0; d < DDIM; d++) zn += z[d] * z[d];

    float best = 3.4e38f;
    int bidx = 0;
    for (int c = 0; c < KCODES / 128; c++) {
        __syncthreads();
        for (int i = tid; i < 128 * DDIM; i += blockDim.x) sE[i] = E[c * 128 * DDIM + i];
        for (int i = tid; i < 128; i += blockDim.x) sN[i] = enorm[c * 128 + i];
        __syncthreads();
        for (int k = 0; k < 128; k++) {
            const float4* e4 = (const float4*)(sE + k * DDIM);
            float a0 = 0.f, a1 = 0.f, a2 = 0.f, a3 = 0.f;
#pragma unroll
            for (int m = 0; m < DDIM / 4; m++) {
                float4 e = e4[m];
                a0 += z[4 * m + 0] * e.x;
                a1 += z[4 * m + 1] * e.y;
                a2 += z[4 * m + 2] * e.z;
                a3 += z[4 * m + 3] * e.w;
            }
            float dist = zn + sN[k] - 2.f * ((a0 + a1) + (a2 + a3));
            if (dist < best) { best = dist; bidx = c * 128 + k; }
        }
    }

    // gather code, write Zq (NCHW), accumulate direct squared error
    float local = 0.f;
    const float* eb = E + (size_t)bidx * DDIM;
    float* zqb = zq + (size_t)n * DDIM * 1024 + hw;
#pragma unroll
    for (int d = 0; d < DDIM; d++) {
        float e = eb[d];
        zqb[(size_t)d * 1024] = e;
        float df = e - z[d];
        local += df * df;
    }
    atomicAdd(&counts[bidx], 1.f);

#pragma unroll
    for (int o = 16; o; o >>= 1) local += __shfl_down_sync(0xffffffffu, local, o);
    if ((tid & 31) == 0) sred[tid >> 5] = local;
    __syncthreads();
    if (tid < 8) {
        local = sred[tid];
#pragma unroll
        for (int o = 4; o; o >>= 1) local += __shfl_down_sync(0xffu, local, o);
        if (tid == 0) atomicAdd(sqsum, local);
    }
}

__global__ void finalize_k(const float* __restrict__ counts, const float* __restrict__ sqsum,
                           float* __restrict__ out)
{
    __shared__ float sred[16];
    int tid = threadIdx.x;  // 512 threads
    float p = counts[tid] * (1.f / 65536.f);
    float term = -p * log2f(p + 1e-10f);
#pragma unroll
    for (int o = 16; o; o >>= 1) term += __shfl_down_sync(0xffffffffu, term, o);
    if ((tid & 31) == 0) sred[tid >> 5] = term;
    __syncthreads();
    if (tid < 16) {
        term = sred[tid];
#pragma unroll
        for (int o = 8; o; o >>= 1) term += __shfl_down_sync(0xffffu, term, o);
        if (tid == 0) {
            float H = term;
            float mse = sqsum[0] / (65536.f * 64.f);
            const int base = 1 + BATCH * 3 * 128 * 128;
            out[0] = 1.25f * mse;       // q + BETA*e, both == mse in forward
            out[base + 0] = mse;        // e_latent_loss
            out[base + 1] = mse;        // q_latent_loss
            out[base + 2] = exp2f(H);   // est_words
        }
    }
}

// ---------------- launch ----------------
extern "C" void kernel_launch(void* const* d_in, const int* in_sizes, int n_in,
                              void* d_out, int out_size)
{
    const float* x        = (const float*)d_in[0];
    const float* enc_w1   = (const float*)d_in[1];
    const float* enc_b1   = (const float*)d_in[2];
    const float* enc_w2   = (const float*)d_in[3];
    const float* enc_b2   = (const float*)d_in[4];
    const float* enc_w3   = (const float*)d_in[5];
    const float* enc_b3   = (const float*)d_in[6];
    const float* enc_w4   = (const float*)d_in[7];
    const float* enc_b4   = (const float*)d_in[8];
    const float* enc_rw1  = (const float*)d_in[9];
    const float* enc_rw2  = (const float*)d_in[10];
    const float* enc_adjw = (const float*)d_in[11];
    const float* enc_adjb = (const float*)d_in[12];
    const float* E        = (const float*)d_in[13];
    const float* dec_adjw = (const float*)d_in[14];
    const float* dec_adjb = (const float*)d_in[15];
    const float* dec_rw1  = (const float*)d_in[16];
    const float* dec_rw2  = (const float*)d_in[17];
    const float* tc1_w    = (const float*)d_in[18];
    const float* tc1_b    = (const float*)d_in[19];
    const float* tc2_w    = (const float*)d_in[20];
    const float* tc2_b    = (const float*)d_in[21];

    float* out   = (float*)d_out;
    float* recon = out + 1;

    float *h1, *a, *b, *mid, *ze, *zq, *enorm, *counts, *sqsum;
    cudaGetSymbolAddress((void**)&h1,     d_h1);
    cudaGetSymbolAddress((void**)&a,      d_a);
    cudaGetSymbolAddress((void**)&b,      d_b);
    cudaGetSymbolAddress((void**)&mid,    d_mid);
    cudaGetSymbolAddress((void**)&ze,     d_ze);
    cudaGetSymbolAddress((void**)&zq,     d_zq);
    cudaGetSymbolAddress((void**)&enorm,  d_enorm);
    cudaGetSymbolAddress((void**)&counts, d_counts);
    cudaGetSymbolAddress((void**)&sqsum,  d_sqsum);

    const int TPB = 128;

    // ---- encoder ----
    // conv1: (B,3,128,128) -> relu -> (B,64,64,64); PX=2
    conv_k<3, 64, 4, 2, 1, 128, 128, 16, 2, false, true, true, false>
        <<<dim3(4096 / (TPB * 2), 64 / 16, BATCH), TPB, 3 * 16 * 16 * 4>>>(x, enc_w1, enc_b1, nullptr, h1);

    // conv2: -> relu -> (B,128,32,32); PX=2
    {
        auto f = conv_k<64, 128, 4, 2, 1, 64, 64, 16, 2, false, true, true, false>;
        cudaFuncSetAttribute((const void*)f, cudaFuncAttributeMaxDynamicSharedMemorySize, 64 * 16 * 16 * 4);
        f<<<dim3(1024 / (TPB * 2), 128 / 16, BATCH), TPB, 64 * 16 * 16 * 4>>>(h1, enc_w2, enc_b2, nullptr, a);
    }
    // conv3: 3x3 relu; PX=4
    {
        auto f = conv_k<128, 128, 3, 1, 1, 32, 32, 16, 4, false, true, true, false>;
        cudaFuncSetAttribute((const void*)f, cudaFuncAttributeMaxDynamicSharedMemorySize, 128 * 9 * 16 * 4);
        f<<<dim3(1024 / (TPB * 4), 128 / 16, BATCH), TPB, 128 * 9 * 16 * 4>>>(a, enc_w3, enc_b3, nullptr, b);
    }
    // conv4: 3x3 no relu; PX=4
    {
        auto f = conv_k<128, 128, 3, 1, 1, 32, 32, 16, 4, false, false, true, false>;
        cudaFuncSetAttribute((const void*)f, cudaFuncAttributeMaxDynamicSharedMemorySize, 128 * 9 * 16 * 4);
        f<<<dim3(1024 / (TPB * 4), 128 / 16, BATCH), TPB, 128 * 9 * 16 * 4>>>(b, enc_w4, enc_b4, nullptr, a);
    }

    auto res_r1 = conv_k<128, 64, 3, 1, 1, 32, 32, 16, 4, true, false, false, false>;
    cudaFuncSetAttribute((const void*)res_r1, cudaFuncAttributeMaxDynamicSharedMemorySize, 128 * 9 * 16 * 4);
    auto res_r2 = conv_k<64, 128, 1, 1, 0, 32, 32, 16, 4, true, false, false, true>;

    // encoder res stack (2 blocks), in-place on `a`
    for (int i = 0; i < 2; i++) {
        res_r1<<<dim3(1024 / (TPB * 4), 64 / 16, BATCH), TPB, 128 * 9 * 16 * 4>>>(
            a, enc_rw1 + (size_t)i * 64 * 128 * 9, nullptr, nullptr, mid);
        res_r2<<<dim3(1024 / (TPB * 4), 128 / 16, BATCH), TPB, 64 * 1 * 16 * 4>>>(
            mid, enc_rw2 + (size_t)i * 128 * 64, nullptr, a, a);
    }
    // enc_adj: relu_in 1x1 -> Ze (B,64,32,32); PX=4
    conv_k<128, 64, 1, 1, 0, 32, 32, 16, 4, true, false, true, false>
        <<<dim3(1024 / (TPB * 4), 64 / 16, BATCH), TPB, 128 * 1 * 16 * 4>>>(a, enc_adjw, enc_adjb, nullptr, ze);

    // ---- VQ ----
    vq_init_k<<<2, 256>>>(E, enorm, counts, sqsum);
    vq_k<<<65536 / 256, 256>>>(ze, E, enorm, zq, counts, sqsum);

    // ---- decoder ----
    // dec_adj 3x3 64->128 bias; PX=4
    conv_k<64, 128, 3, 1, 1, 32, 32, 16, 4, false, false, true, false>
        <<<dim3(1024 / (TPB * 4), 128 / 16, BATCH), TPB, 64 * 9 * 16 * 4>>>(zq, dec_adjw, dec_adjb, nullptr, a);

    for (int i = 0; i < 2; i++) {
        res_r1<<<dim3(1024 / (TPB * 4), 64 / 16, BATCH), TPB, 128 * 9 * 16 * 4>>>(
            a, dec_rw1 + (size_t)i * 64 * 128 * 9, nullptr, nullptr, mid);
        res_r2<<<dim3(1024 / (TPB * 4), 128 / 16, BATCH), TPB, 64 * 1 * 16 * 4>>>(
            mid, dec_rw2 + (size_t)i * 128 * 64, nullptr, a, a);
    }

    // tc1: relu_in (final res relu), convT 128->64, relu_out -> (B,64,64,64); PX=4
    {
        auto f = convt_k<128, 64, 32, 32, 16, 4, true, true, true>;
        cudaFuncSetAttribute((const void*)f, cudaFuncAttributeMaxDynamicSharedMemorySize, 128 * 16 * 16 * 4);
        f<<<dim3(4096 / (TPB * 4), 64 / 16, BATCH), TPB, 128 * 16 * 16 * 4>>>(a, tc1_w, tc1_b, h1);
    }
    // tc2: convT 64->3 -> recon (B,3,128,128); PX=4, scalar stores (recon is +1 float misaligned)
    convt_k<64, 3, 64, 64, 4, 4, false, false, false>
        <<<dim3(16384 / (TPB * 4), 1, BATCH), TPB, 64 * 16 * 4 * 4>>>(h1, tc2_w, tc2_b, recon);

    // ---- scalars ----
    finalize_k<<<1, 512>>>(counts, sqsum, out);
}

// round 3
// speedup vs baseline: 1.5643x; 1.5086x over previous
#include <cuda_runtime.h>
#include <math.h>

#define BATCH 64
#define KCODES 512
#define DDIM 64

// ---------------- scratch (device globals; no allocation allowed) ----------------
__device__ float d_h1 [BATCH * 64 * 64 * 64];   // (B,64,64,64)  also tc1 output
__device__ float d_a  [BATCH * 128 * 32 * 32];  // (B,128,32,32) ping
__device__ float d_b  [BATCH * 128 * 32 * 32];  // (B,128,32,32) pong
__device__ float d_mid[BATCH * 64 * 32 * 32];   // res-block mid (B,64,32,32)
__device__ float d_ze [BATCH * 64 * 32 * 32];   // encoder latent
__device__ float d_zq [BATCH * 64 * 32 * 32];   // quantized latent
__device__ float d_enorm [KCODES];
__device__ float d_counts[KCODES];
__device__ float d_sqsum[1];

// ---------------- packed f32x2 helpers ----------------
__device__ __forceinline__ unsigned long long pk2(float a, float b) {
    unsigned long long r;
    asm("mov.b64 %0, {%1, %2};" : "=l"(r) : "f"(a), "f"(b));
    return r;
}
__device__ __forceinline__ void fma2(unsigned long long& d, unsigned long long a, unsigned long long b) {
    asm("fma.rn.f32x2 %0, %1, %2, %0;" : "+l"(d) : "l"(a), "l"(b));
}
__device__ __forceinline__ float2 upk2(unsigned long long a) {
    float2 f;
    asm("mov.b64 {%0, %1}, %2;" : "=f"(f.x), "=f"(f.y) : "l"(a));
    return f;
}

// ========== specialized 3x3 stride-1 pad-1 conv on 32x32 planes ==========
// 256 threads = whole plane, PX=4, CO_BLK=16. Vector float4 input loads +
// shfl halo exchange (8 lanes per image row).
template<int CIN, int COUT, bool RELU_IN, bool RELU_OUT, bool HAS_BIAS, bool ADD_RES>
__global__ void __launch_bounds__(256) conv3_k(
    const float* __restrict__ in, const float* __restrict__ w,
    const float* __restrict__ bias, const float* __restrict__ res,
    float* __restrict__ out)
{
    constexpr int CO_BLK = 16;
    extern __shared__ float sw[];  // [CIN][9][CO_BLK]

    const int n   = blockIdx.z;
    const int co0 = blockIdx.y * CO_BLK;
    const int tid = threadIdx.x;

    for (int i = tid; i < CIN * 9 * CO_BLK; i += 256) {
        int co = i % CO_BLK;
        int t  = (i / CO_BLK) % 9;
        int ci = i / (CO_BLK * 9);
        sw[i] = w[((size_t)(co0 + co) * CIN + ci) * 9 + t];
    }
    __syncthreads();

    const int oy  = tid >> 3;        // 0..31
    const int l   = tid & 7;         // lane-in-row
    const int ox0 = l * 4;
    const int p0  = oy * 32 + ox0;   // == tid*4

    unsigned long long acc[4][8];
#pragma unroll
    for (int px = 0; px < 4; px++)
#pragma unroll
        for (int j = 0; j < 8; j++) acc[px][j] = 0ull;

    const float* inb = in + (size_t)n * CIN * 1024;
    for (int ci = 0; ci < CIN; ci++) {
        const float* inc = inb + (size_t)ci * 1024;
        const ulonglong2* wt = (const ulonglong2*)(sw + (size_t)ci * 9 * CO_BLK);
#pragma unroll
        for (int ky = 0; ky < 3; ky++) {
            const int y = oy + ky - 1;
            const bool yok = (y >= 0) && (y < 32);
            float4 v4 = make_float4(0.f, 0.f, 0.f, 0.f);
            if (yok) v4 = *(const float4*)(inc + y * 32 + ox0);
            if (RELU_IN) {
                v4.x = fmaxf(v4.x, 0.f); v4.y = fmaxf(v4.y, 0.f);
                v4.z = fmaxf(v4.z, 0.f); v4.w = fmaxf(v4.w, 0.f);
            }
            float lf = __shfl_up_sync(0xffffffffu, v4.w, 1);
            float rf = __shfl_down_sync(0xffffffffu, v4.x, 1);
            if (l == 0) lf = 0.f;
            if (l == 7) rf = 0.f;
            unsigned long long pv[6];
            pv[0] = pk2(lf, lf);
            pv[1] = pk2(v4.x, v4.x);
            pv[2] = pk2(v4.y, v4.y);
            pv[3] = pk2(v4.z, v4.z);
            pv[4] = pk2(v4.w, v4.w);
            pv[5] = pk2(rf, rf);
#pragma unroll
            for (int kx = 0; kx < 3; kx++) {
                const int t = ky * 3 + kx;
#pragma unroll
                for (int q = 0; q < 4; q++) {
                    ulonglong2 ww = wt[t * 4 + q];
#pragma unroll
                    for (int px = 0; px < 4; px++) {
                        fma2(acc[px][2 * q + 0], pv[px + kx], ww.x);
                        fma2(acc[px][2 * q + 1], pv[px + kx], ww.y);
                    }
                }
            }
        }
    }

    float bco[CO_BLK];
#pragma unroll
    for (int c = 0; c < CO_BLK; c++) bco[c] = HAS_BIAS ? bias[co0 + c] : 0.f;

    float* ob = out + ((size_t)n * COUT + co0) * 1024 + p0;
#pragma unroll
    for (int j = 0; j < 8; j++) {
        float r0[4], r1[4];
#pragma unroll
        for (int px = 0; px < 4; px++) {
            float2 f = upk2(acc[px][j]);
            r0[px] = f.x + bco[2 * j + 0];
            r1[px] = f.y + bco[2 * j + 1];
            if (ADD_RES) {
                r0[px] += res[((size_t)n * COUT + co0 + 2 * j + 0) * 1024 + p0 + px];
                r1[px] += res[((size_t)n * COUT + co0 + 2 * j + 1) * 1024 + p0 + px];
            }
            if (RELU_OUT) { r0[px] = fmaxf(r0[px], 0.f); r1[px] = fmaxf(r1[px], 0.f); }
        }
        *(float4*)(ob + (size_t)(2 * j + 0) * 1024) = make_float4(r0[0], r0[1], r0[2], r0[3]);
        *(float4*)(ob + (size_t)(2 * j + 1) * 1024) = make_float4(r1[0], r1[1], r1[2], r1[3]);
    }
}

// ---------------- generic direct conv, PX pixels/thread, f32x2 MACs ----------------
template<int CIN, int COUT, int KS, int STR, int PAD, int IH, int IW, int CO_BLK, int PX,
         bool RELU_IN, bool RELU_OUT, bool HAS_BIAS, bool ADD_RES>
__global__ void __launch_bounds__(256) conv_k(
    const float* __restrict__ in, const float* __restrict__ w,
    const float* __restrict__ bias, const float* __restrict__ res,
    float* __restrict__ out)
{
    static_assert(CO_BLK % 4 == 0, "co blk mult of 4");
    static_assert(COUT % CO_BLK == 0, "cout divisible");
    constexpr int OH = (IH + 2 * PAD - KS) / STR + 1;
    constexpr int OW = (IW + 2 * PAD - KS) / STR + 1;
    static_assert(OW % PX == 0, "row-aligned pixel tiles");
    constexpr int KK = KS * KS;
    constexpr int COLS = STR * (PX - 1) + KS;
    extern __shared__ float sw[];  // [CIN][KK][CO_BLK]

    const int n   = blockIdx.z;
    const int co0 = blockIdx.y * CO_BLK;
    const int tid = threadIdx.x;

    for (int i = tid; i < CIN * KK * CO_BLK; i += blockDim.x) {
        int co = i % CO_BLK;
        int t  = (i / CO_BLK) % KK;
        int ci = i / (CO_BLK * KK);
        sw[i] = w[((size_t)(co0 + co) * CIN + ci) * KK + t];
    }
    __syncthreads();

    int p0 = (blockIdx.x * blockDim.x + tid) * PX;
    if (p0 >= OH * OW) return;
    int oy = p0 / OW, ox0 = p0 % OW;
    int iy0 = oy * STR - PAD, ix0 = ox0 * STR - PAD;

    bool rok[KS]; int roff[KS];
#pragma unroll
    for (int ky = 0; ky < KS; ky++) {
        int y = iy0 + ky;
        rok[ky] = (y >= 0) && (y < IH);
        roff[ky] = y * IW;
    }
    bool cok[COLS]; int coff[COLS];
#pragma unroll
    for (int cx = 0; cx < COLS; cx++) {
        int x = ix0 + cx;
        cok[cx] = (x >= 0) && (x < IW);
        coff[cx] = x;
    }

    unsigned long long acc[PX][CO_BLK / 2];
#pragma unroll
    for (int px = 0; px < PX; px++)
#pragma unroll
        for (int j = 0; j < CO_BLK / 2; j++) acc[px][j] = 0ull;

    const float* inb = in + (size_t)n * CIN * IH * IW;
    for (int ci = 0; ci < CIN; ci++) {
        const float* inc = inb + (size_t)ci * IH * IW;
        const ulonglong2* wt = (const ulonglong2*)(sw + (size_t)ci * KK * CO_BLK);
#pragma unroll
        for (int ky = 0; ky < KS; ky++) {
            unsigned long long pv[COLS];
#pragma unroll
            for (int cx = 0; cx < COLS; cx++) {
                float val = (rok[ky] && cok[cx]) ? inc[roff[ky] + coff[cx]] : 0.f;
                if (RELU_IN) val = fmaxf(val, 0.f);
                pv[cx] = pk2(val, val);
            }
#pragma unroll
            for (int kx = 0; kx < KS; kx++) {
                const int t = ky * KS + kx;
#pragma unroll
                for (int q = 0; q < CO_BLK / 4; q++) {
                    ulonglong2 ww = wt[t * (CO_BLK / 4) + q];
#pragma unroll
                    for (int px = 0; px < PX; px++) {
                        unsigned long long vv = pv[px * STR + kx];
                        fma2(acc[px][2 * q + 0], vv, ww.x);
                        fma2(acc[px][2 * q + 1], vv, ww.y);
                    }
                }
            }
        }
    }

    float bco[CO_BLK];
#pragma unroll
    for (int c = 0; c < CO_BLK; c++) bco[c] = HAS_BIAS ? bias[co0 + c] : 0.f;

    float* ob = out + ((size_t)n * COUT + co0) * OH * OW + p0;
#pragma unroll
    for (int j = 0; j < CO_BLK / 2; j++) {
        float r0[PX], r1[PX];
#pragma unroll
        for (int px = 0; px < PX; px++) {
            float2 f = upk2(acc[px][j]);
            r0[px] = f.x + bco[2 * j + 0];
            r1[px] = f.y + bco[2 * j + 1];
            if (ADD_RES) {
                r0[px] += res[((size_t)n * COUT + co0 + 2 * j + 0) * OH * OW + p0 + px];
                r1[px] += res[((size_t)n * COUT + co0 + 2 * j + 1) * OH * OW + p0 + px];
            }
            if (RELU_OUT) { r0[px] = fmaxf(r0[px], 0.f); r1[px] = fmaxf(r1[px], 0.f); }
        }
        float* o0 = ob + (size_t)(2 * j + 0) * OH * OW;
        float* o1 = ob + (size_t)(2 * j + 1) * OH * OW;
        if (PX == 4) {
            *(float4*)o0 = make_float4(r0[0], r0[1], r0[2], r0[3 % PX]);
            *(float4*)o1 = make_float4(r1[0], r1[1], r1[2], r1[3 % PX]);
        } else if (PX == 2) {
            *(float2*)o0 = make_float2(r0[0], r0[1 % PX]);
            *(float2*)o1 = make_float2(r1[0], r1[1 % PX]);
        } else {
#pragma unroll
            for (int px = 0; px < PX; px++) { o0[px] = r0[px]; o1[px] = r1[px]; }
        }
    }
}

// ---------------- transposed conv, k=4, s=2, p=1 (gather), PX pixels, f32x2 ----------------
template<int CIN, int COUT, int IH, int IW, int CO_BLK, int PX,
         bool RELU_IN, bool RELU_OUT, bool VEC_ST>
__global__ void __launch_bounds__(256) convt_k(
    const float* __restrict__ in, const float* __restrict__ w,
    const float* __restrict__ bias, float* __restrict__ out)
{
    static_assert(CO_BLK % 4 == 0, "co blk mult of 4");
    static_assert(PX % 2 == 0, "pixel pairs");
    constexpr int OH = IH * 2, OW = IW * 2;
    static_assert(OW % PX == 0, "row-aligned");
    extern __shared__ float sw[];  // [CIN][16][CO_BLK]

    const int n   = blockIdx.z;
    const int co0 = blockIdx.y * CO_BLK;
    const int tid = threadIdx.x;

    for (int i = tid; i < CIN * 16 * CO_BLK; i += blockDim.x) {
        int co = i % CO_BLK;
        int t  = (i / CO_BLK) % 16;
        int ci = i / (CO_BLK * 16);
        float val = 0.f;
        if (co0 + co < COUT)
            val = w[((size_t)ci * COUT + (co0 + co)) * 16 + t];
        sw[i] = val;
    }
    __syncthreads();

    int p0 = (blockIdx.x * blockDim.x + tid) * PX;
    if (p0 >= OH * OW) return;
    int oy = p0 / OW, ox0 = p0 % OW;
    const int kpy = (oy + 1) & 1;
    const int kp0 = (ox0 + 1) & 1;

    int iy[2]; bool vy[2];
#pragma unroll
    for (int a = 0; a < 2; a++) {
        int ky = kpy + 2 * a, yy = oy + 1 - ky;
        iy[a] = yy >> 1; vy[a] = (yy >= 0) && (iy[a] < IH);
    }
    int ixp[PX][2]; bool vxp[PX][2];
#pragma unroll
    for (int px = 0; px < PX; px++) {
        int ox = ox0 + px;
        int kpx = (kp0 + px) & 1;
#pragma unroll
        for (int b = 0; b < 2; b++) {
            int kx = kpx + 2 * b, xx = ox + 1 - kx;
            ixp[px][b] = xx >> 1; vxp[px][b] = (xx >= 0) && (ixp[px][b] < IW);
        }
    }

    unsigned long long acc[PX][CO_BLK / 2];
#pragma unroll
    for (int px = 0; px < PX; px++)
#pragma unroll
        for (int j = 0; j < CO_BLK / 2; j++) acc[px][j] = 0ull;

    const float* inb = in + (size_t)n * CIN * IH * IW;
    for (int ci = 0; ci < CIN; ci++) {
        const float* inc = inb + (size_t)ci * IH * IW;
        unsigned long long pv[PX][4];
#pragma unroll
        for (int px = 0; px < PX; px++)
#pragma unroll
            for (int a = 0; a < 2; a++)
#pragma unroll
                for (int b = 0; b < 2; b++) {
                    float val = 0.f;
                    if (vy[a] && vxp[px][b]) val = inc[iy[a] * IW + ixp[px][b]];
                    if (RELU_IN) val = fmaxf(val, 0.f);
                    pv[px][a * 2 + b] = pk2(val, val);
                }
        const ulonglong2* wt = (const ulonglong2*)(sw + (size_t)ci * 16 * CO_BLK);
#pragma unroll
        for (int g = 0; g < 2; g++) {
            const int kpxg = (kp0 + g) & 1;
#pragma unroll
            for (int a = 0; a < 2; a++)
#pragma unroll
                for (int b = 0; b < 2; b++) {
                    const int t = (kpy + 2 * a) * 4 + (kpxg + 2 * b);
#pragma unroll
                    for (int q = 0; q < CO_BLK / 4; q++) {
                        ulonglong2 ww = wt[t * (CO_BLK / 4) + q];
#pragma unroll
                        for (int px = g; px < PX; px += 2) {
                            unsigned long long vv = pv[px][a * 2 + b];
                            fma2(acc[px][2 * q + 0], vv, ww.x);
                            fma2(acc[px][2 * q + 1], vv, ww.y);
                        }
                    }
                }
        }
    }

    float bco[CO_BLK];
#pragma unroll
    for (int c = 0; c < CO_BLK; c++)
        bco[c] = (co0 + c < COUT) ? bias[co0 + c] : 0.f;

    float* ob = out + ((size_t)n * COUT + co0) * OH * OW + p0;
#pragma unroll
    for (int j = 0; j < CO_BLK / 2; j++) {
        float r0[PX], r1[PX];
#pragma unroll
        for (int px = 0; px < PX; px++) {
            float2 f = upk2(acc[px][j]);
            r0[px] = f.x + bco[2 * j + 0];
            r1[px] = f.y + bco[2 * j + 1];
            if (RELU_OUT) { r0[px] = fmaxf(r0[px], 0.f); r1[px] = fmaxf(r1[px], 0.f); }
        }
        float* o0 = ob + (size_t)(2 * j + 0) * OH * OW;
        float* o1 = ob + (size_t)(2 * j + 1) * OH * OW;
        if (VEC_ST && PX == 4) {
            if (co0 + 2 * j + 0 < COUT) *(float4*)o0 = make_float4(r0[0], r0[1], r0[2], r0[3 % PX]);
            if (co0 + 2 * j + 1 < COUT) *(float4*)o1 = make_float4(r1[0], r1[1], r1[2], r1[3 % PX]);
        } else {
#pragma unroll
            for (int px = 0; px < PX; px++) {
                if (co0 + 2 * j + 0 < COUT) o0[px] = r0[px];
                if (co0 + 2 * j + 1 < COUT) o1[px] = r1[px];
            }
        }
    }
}

// ---------------- VQ ----------------
__global__ void vq_init_k(const float* __restrict__ E, float* __restrict__ enorm,
                          float* __restrict__ counts, float* __restrict__ sqsum)
{
    int k = blockIdx.x * blockDim.x + threadIdx.x;
    if (k < KCODES) {
        float s = 0.f;
#pragma unroll
        for (int d = 0; d < DDIM; d++) { float e = E[k * DDIM + d]; s += e * e; }
        enorm[k] = s;
        counts[k] = 0.f;
    }
    if (k == 0) sqsum[0] = 0.f;
}

__global__ void vq_k(const float* __restrict__ ze, const float* __restrict__ E,
                     const float* __restrict__ enorm, float* __restrict__ zq,
                     float* __restrict__ counts, float* __restrict__ sqsum)
{
    __shared__ float sE[128 * DDIM];
    __shared__ float sN[128];
    __shared__ float sred[8];

    const int tid = threadIdx.x;
    const int r = blockIdx.x * blockDim.x + tid;  // 0..65535
    const int n = r >> 10, hw = r & 1023;

    const float* zb = ze + (size_t)n * DDIM * 1024 + hw;
    float z[DDIM];
#pragma unroll
    for (int d = 0; d < DDIM; d++) z[d] = zb[(size_t)d * 1024];
    float zn = 0.f;
#pragma unroll
    for (int d = 0; d < DDIM; d++) zn += z[d] * z[d];

    float best = 3.4e38f;
    int bidx = 0;
    for (int c = 0; c < KCODES / 128; c++) {
        __syncthreads();
        for (int i = tid; i < 128 * DDIM; i += blockDim.x) sE[i] = E[c * 128 * DDIM + i];
        for (int i = tid; i < 128; i += blockDim.x) sN[i] = enorm[c * 128 + i];
        __syncthreads();
        for (int k = 0; k < 128; k++) {
            const float4* e4 = (const float4*)(sE + k * DDIM);
            float a0 = 0.f, a1 = 0.f, a2 = 0.f, a3 = 0.f;
#pragma unroll
            for (int m = 0; m < DDIM / 4; m++) {
                float4 e = e4[m];
                a0 += z[4 * m + 0] * e.x;
                a1 += z[4 * m + 1] * e.y;
                a2 += z[4 * m + 2] * e.z;
                a3 += z[4 * m + 3] * e.w;
            }
            float dist = zn + sN[k] - 2.f * ((a0 + a1) + (a2 + a3));
            if (dist < best) { best = dist; bidx = c * 128 + k; }
        }
    }

    float local = 0.f;
    const float* eb = E + (size_t)bidx * DDIM;
    float* zqb = zq + (size_t)n * DDIM * 1024 + hw;
#pragma unroll
    for (int d = 0; d < DDIM; d++) {
        float e = eb[d];
        zqb[(size_t)d * 1024] = e;
        float df = e - z[d];
        local += df * df;
    }
    atomicAdd(&counts[bidx], 1.f);

#pragma unroll
    for (int o = 16; o; o >>= 1) local += __shfl_down_sync(0xffffffffu, local, o);
    if ((tid & 31) == 0) sred[tid >> 5] = local;
    __syncthreads();
    if (tid < 8) {
        local = sred[tid];
#pragma unroll
        for (int o = 4; o; o >>= 1) local += __shfl_down_sync(0xffu, local, o);
        if (tid == 0) atomicAdd(sqsum, local);
    }
}

__global__ void finalize_k(const float* __restrict__ counts, const float* __restrict__ sqsum,
                           float* __restrict__ out)
{
    __shared__ float sred[16];
    int tid = threadIdx.x;  // 512 threads
    float p = counts[tid] * (1.f / 65536.f);
    float term = -p * log2f(p + 1e-10f);
#pragma unroll
    for (int o = 16; o; o >>= 1) term += __shfl_down_sync(0xffffffffu, term, o);
    if ((tid & 31) == 0) sred[tid >> 5] = term;
    __syncthreads();
    if (tid < 16) {
        term = sred[tid];
#pragma unroll
        for (int o = 8; o; o >>= 1) term += __shfl_down_sync(0xffffu, term, o);
        if (tid == 0) {
            float H = term;
            float mse = sqsum[0] / (65536.f * 64.f);
            const int base = 1 + BATCH * 3 * 128 * 128;
            out[0] = 1.25f * mse;
            out[base + 0] = mse;
            out[base + 1] = mse;
            out[base + 2] = exp2f(H);
        }
    }
}

// ---------------- launch ----------------
extern "C" void kernel_launch(void* const* d_in, const int* in_sizes, int n_in,
                              void* d_out, int out_size)
{
    const float* x        = (const float*)d_in[0];
    const float* enc_w1   = (const float*)d_in[1];
    const float* enc_b1   = (const float*)d_in[2];
    const float* enc_w2   = (const float*)d_in[3];
    const float* enc_b2   = (const float*)d_in[4];
    const float* enc_w3   = (const float*)d_in[5];
    const float* enc_b3   = (const float*)d_in[6];
    const float* enc_w4   = (const float*)d_in[7];
    const float* enc_b4   = (const float*)d_in[8];
    const float* enc_rw1  = (const float*)d_in[9];
    const float* enc_rw2  = (const float*)d_in[10];
    const float* enc_adjw = (const float*)d_in[11];
    const float* enc_adjb = (const float*)d_in[12];
    const float* E        = (const float*)d_in[13];
    const float* dec_adjw = (const float*)d_in[14];
    const float* dec_adjb = (const float*)d_in[15];
    const float* dec_rw1  = (const float*)d_in[16];
    const float* dec_rw2  = (const float*)d_in[17];
    const float* tc1_w    = (const float*)d_in[18];
    const float* tc1_b    = (const float*)d_in[19];
    const float* tc2_w    = (const float*)d_in[20];
    const float* tc2_b    = (const float*)d_in[21];

    float* out   = (float*)d_out;
    float* recon = out + 1;

    float *h1, *a, *b, *mid, *ze, *zq, *enorm, *counts, *sqsum;
    cudaGetSymbolAddress((void**)&h1,     d_h1);
    cudaGetSymbolAddress((void**)&a,      d_a);
    cudaGetSymbolAddress((void**)&b,      d_b);
    cudaGetSymbolAddress((void**)&mid,    d_mid);
    cudaGetSymbolAddress((void**)&ze,     d_ze);
    cudaGetSymbolAddress((void**)&zq,     d_zq);
    cudaGetSymbolAddress((void**)&enorm,  d_enorm);
    cudaGetSymbolAddress((void**)&counts, d_counts);
    cudaGetSymbolAddress((void**)&sqsum,  d_sqsum);

    const int TPB = 256;

    // ---- encoder ----
    // conv1: (B,3,128,128) -> relu -> (B,64,64,64); PX=2
    conv_k<3, 64, 4, 2, 1, 128, 128, 16, 2, false, true, true, false>
        <<<dim3(4096 / (TPB * 2), 64 / 16, BATCH), TPB, 3 * 16 * 16 * 4>>>(x, enc_w1, enc_b1, nullptr, h1);

    // conv2: -> relu -> (B,128,32,32); PX=2
    {
        auto f = conv_k<64, 128, 4, 2, 1, 64, 64, 16, 2, false, true, true, false>;
        cudaFuncSetAttribute((const void*)f, cudaFuncAttributeMaxDynamicSharedMemorySize, 64 * 16 * 16 * 4);
        f<<<dim3(1024 / (TPB * 2), 128 / 16, BATCH), TPB, 64 * 16 * 16 * 4>>>(h1, enc_w2, enc_b2, nullptr, a);
    }
    // conv3: 3x3 relu (specialized)
    {
        auto f = conv3_k<128, 128, false, true, true, false>;
        cudaFuncSetAttribute((const void*)f, cudaFuncAttributeMaxDynamicSharedMemorySize, 128 * 9 * 16 * 4);
        f<<<dim3(1, 128 / 16, BATCH), TPB, 128 * 9 * 16 * 4>>>(a, enc_w3, enc_b3, nullptr, b);
    }
    // conv4: 3x3 no relu (specialized)
    {
        auto f = conv3_k<128, 128, false, false, true, false>;
        cudaFuncSetAttribute((const void*)f, cudaFuncAttributeMaxDynamicSharedMemorySize, 128 * 9 * 16 * 4);
        f<<<dim3(1, 128 / 16, BATCH), TPB, 128 * 9 * 16 * 4>>>(b, enc_w4, enc_b4, nullptr, a);
    }

    auto res_r1 = conv3_k<128, 64, true, false, false, false>;
    cudaFuncSetAttribute((const void*)res_r1, cudaFuncAttributeMaxDynamicSharedMemorySize, 128 * 9 * 16 * 4);
    auto res_r2 = conv_k<64, 128, 1, 1, 0, 32, 32, 16, 4, true, false, false, true>;

    // encoder res stack (2 blocks), in-place on `a`
    for (int i = 0; i < 2; i++) {
        res_r1<<<dim3(1, 64 / 16, BATCH), TPB, 128 * 9 * 16 * 4>>>(
            a, enc_rw1 + (size_t)i * 64 * 128 * 9, nullptr, nullptr, mid);
        res_r2<<<dim3(1, 128 / 16, BATCH), TPB, 64 * 1 * 16 * 4>>>(
            mid, enc_rw2 + (size_t)i * 128 * 64, nullptr, a, a);
    }
    // enc_adj: relu_in 1x1 -> Ze (B,64,32,32); PX=4
    conv_k<128, 64, 1, 1, 0, 32, 32, 16, 4, true, false, true, false>
        <<<dim3(1, 64 / 16, BATCH), TPB, 128 * 1 * 16 * 4>>>(a, enc_adjw, enc_adjb, nullptr, ze);

    // ---- VQ ----
    vq_init_k<<<2, 256>>>(E, enorm, counts, sqsum);
    vq_k<<<65536 / 256, 256>>>(ze, E, enorm, zq, counts, sqsum);

    // ---- decoder ----
    // dec_adj 3x3 64->128 bias (specialized)
    {
        auto f = conv3_k<64, 128, false, false, true, false>;
        cudaFuncSetAttribute((const void*)f, cudaFuncAttributeMaxDynamicSharedMemorySize, 64 * 9 * 16 * 4);
        f<<<dim3(1, 128 / 16, BATCH), TPB, 64 * 9 * 16 * 4>>>(zq, dec_adjw, dec_adjb, nullptr, a);
    }

    for (int i = 0; i < 2; i++) {
        res_r1<<<dim3(1, 64 / 16, BATCH), TPB, 128 * 9 * 16 * 4>>>(
            a, dec_rw1 + (size_t)i * 64 * 128 * 9, nullptr, nullptr, mid);
        res_r2<<<dim3(1, 128 / 16, BATCH), TPB, 64 * 1 * 16 * 4>>>(
            mid, dec_rw2 + (size_t)i * 128 * 64, nullptr, a, a);
    }

    // tc1: relu_in, convT 128->64, relu_out -> (B,64,64,64); PX=4
    {
        auto f = convt_k<128, 64, 32, 32, 16, 4, true, true, true>;
        cudaFuncSetAttribute((const void*)f, cudaFuncAttributeMaxDynamicSharedMemorySize, 128 * 16 * 16 * 4);
        f<<<dim3(4096 / (TPB * 4), 64 / 16, BATCH), TPB, 128 * 16 * 16 * 4>>>(a, tc1_w, tc1_b, h1);
    }
    // tc2: convT 64->3 -> recon (B,3,128,128); PX=4, scalar stores (recon is +1 float misaligned)
    convt_k<64, 3, 64, 64, 4, 4, false, false, false>
        <<<dim3(16384 / (TPB * 4), 1, BATCH), TPB, 64 * 16 * 4 * 4>>>(h1, tc2_w, tc2_b, recon);

    // ---- scalars ----
    finalize_k<<<1, 512>>>(counts, sqsum, out);
}